// round 16
// baseline (speedup 1.0000x reference)
#include <cuda_runtime.h>
#include <cuda_fp16.h>
#include <stdint.h>

#define HW     1444
#define KDIM   512
#define NOUT   255
#define BM     64
#define KC     32
#define NCH    16
#define THREADS 256
#define NTILES 722

#define S_ARAW(st) ((st)*8192)
#define S_A16(s)   (24576 + (s)*5120)
#define S_B(st)    (34816 + (st)*20480)
#define S_STAGE    0
#define S_BIAS     96256
#define S_TOTAL    97280

__device__ __half g_Bh[256 * KDIM];
__constant__ float c_anch[3][2] = {{30.0f, 61.0f}, {62.0f, 45.0f}, {59.0f, 119.0f}};

static __device__ __forceinline__ uint32_t smem_u32(const void* p) {
    uint32_t a;
    asm("{ .reg .u64 t; cvta.to.shared.u64 t, %1; cvt.u32.u64 %0, t; }" : "=r"(a) : "l"(p));
    return a;
}
static __device__ __forceinline__ uint32_t pack2h(__half a, __half b) {
    __half2 p = __halves2half2(a, b);
    return *reinterpret_cast<uint32_t*>(&p);
}

#define LDM_X4(r0, r1, r2, r3, addr)                                        \
    asm volatile("ldmatrix.sync.aligned.m8n8.x4.shared.b16 {%0,%1,%2,%3}, [%4];" \
                 : "=r"(r0), "=r"(r1), "=r"(r2), "=r"(r3) : "r"(addr))
#define MMA16816(c, a, b)                                                   \
    asm volatile("mma.sync.aligned.m16n8k16.row.col.f32.f16.f16.f32 "       \
                 "{%0,%1,%2,%3},{%4,%5,%6,%7},{%8,%9},{%0,%1,%2,%3};"       \
                 : "+f"((c)[0]), "+f"((c)[1]), "+f"((c)[2]), "+f"((c)[3])   \
                 : "r"((a)[0]), "r"((a)[1]), "r"((a)[2]), "r"((a)[3]),      \
                   "r"((b)[0]), "r"((b)[1]))
#define CP16(dst, src)                                                      \
    asm volatile("cp.async.cg.shared.global [%0], [%1], 16;" :: "r"(dst), "l"(src))
#define CP4(dst, src)                                                       \
    asm volatile("cp.async.ca.shared.global [%0], [%1], 4;" :: "r"(dst), "l"(src))
#define CP_COMMIT() asm volatile("cp.async.commit_group;" ::: "memory")
#define CP_WAIT0()  asm volatile("cp.async.wait_group 0;" ::: "memory")
#define CP_WAIT1()  asm volatile("cp.async.wait_group 1;" ::: "memory")

__global__ void prep_w(const float* __restrict__ w) {
    const int t = blockIdx.x * 256 + threadIdx.x;
    const int n = t >> 9;
    const int k = t & 511;
    float a = (n < NOUT) ? w[n * KDIM + k] : 0.0f;
    g_Bh[t] = __float2half_rn(a);
}

// A raw: 32 k-rows x 64 m (256B) per chunk; handles image-boundary straddle.
static __device__ __forceinline__ void issue_A(uint32_t sb, int tid, int chunk,
                                               const float* __restrict__ xin,
                                               int b0, int hw0, int split) {
    const uint32_t dstb = sb + S_ARAW(chunk % 3);
    #pragma unroll
    for (int it = 0; it < 2; it++) {
        const int idx = it * 256 + tid;          // 0..511
        const int k   = idx >> 4;                // 0..31
        const int c   = idx & 15;                // 16B unit: m-range [4c, 4c+4)
        const int kg  = chunk * KC + k;
        const uint32_t dst = dstb + k * 256 + c * 16;
        const int mlo = c * 4;
        if (mlo + 4 <= split) {
            CP16(dst, xin + ((size_t)b0 * KDIM + kg) * HW + hw0 + mlo);
        } else if (mlo >= split) {
            CP16(dst, xin + ((size_t)(b0 + 1) * KDIM + kg) * HW + (mlo - split));
        } else {
            #pragma unroll
            for (int q = 0; q < 4; q++) {
                const int m = mlo + q;
                const float* s = (m < split)
                    ? xin + ((size_t)b0 * KDIM + kg) * HW + hw0 + m
                    : xin + ((size_t)(b0 + 1) * KDIM + kg) * HW + (m - split);
                CP4(dst + q * 4, s);
            }
        }
    }
}

static __device__ __forceinline__ void issue_B(uint32_t sb, int tid, int chunk) {
    const uint32_t dstb = sb + S_B(chunk % 3);
    #pragma unroll
    for (int it = 0; it < 4; it++) {
        const int idx = it * 256 + tid;
        const int n   = idx >> 2;
        const int c   = idx & 3;
        const __half* src = g_Bh + n * KDIM + chunk * KC + c * 8;
        CP16(dstb + n * 80 + ((c ^ ((n >> 3) & 3)) << 4), src);
    }
}

__global__ __launch_bounds__(THREADS, 2)
void yolo_mma_kernel(const float* __restrict__ xin,
                     const float* __restrict__ bias,
                     float* __restrict__ out)
{
    extern __shared__ __align__(128) unsigned char smem[];
    const uint32_t sb = smem_u32(smem);
    const int tid = threadIdx.x;
    const int lid = tid & 31;
    const int wid = tid >> 5;
    const int m0  = blockIdx.x * BM;
    const int b0  = m0 / HW;
    const int hw0 = m0 - b0 * HW;
    const int split = (hw0 + BM <= HW) ? BM : (HW - hw0);

    if (tid < NOUT) ((float*)(smem + S_BIAS))[tid] = bias[tid];

    const int mC   = tid & 63;
    const int kq   = tid >> 6;
    const int cKey = (mC >> 3) & 3;

    const int wm = wid & 1;
    const int wn = wid >> 1;
    const int a_r = (lid & 7) | (((lid >> 3) & 1) << 3);
    const int a_c = lid >> 4;
    const int b_n = (lid & 7) | ((lid >> 4) << 3);
    const int b_h = (lid >> 3) & 1;

    float acc[2][8][4];
    #pragma unroll
    for (int mt = 0; mt < 2; mt++)
        #pragma unroll
        for (int nt = 0; nt < 8; nt++)
            #pragma unroll
            for (int e = 0; e < 4; e++) acc[mt][nt][e] = 0.0f;

    issue_A(sb, tid, 0, xin, b0, hw0, split); issue_B(sb, tid, 0); CP_COMMIT();
    issue_A(sb, tid, 1, xin, b0, hw0, split); issue_B(sb, tid, 1); CP_COMMIT();
    CP_WAIT1();
    __syncthreads();   // cross-thread visibility of group-0 cp.async before convert
    {
        const unsigned char* raw = smem + S_ARAW(0);
        #pragma unroll
        for (int j = 0; j < 4; j++) {
            const int kk = 2 * (kq + 4 * j);
            const float a0 = *(const float*)(raw + kk * 256 + mC * 4);
            const float a1 = *(const float*)(raw + (kk + 1) * 256 + mC * 4);
            const uint32_t off = (uint32_t)(mC * 80 + ((j ^ cKey) << 4) + kq * 4);
            *(uint32_t*)(smem + S_A16(0) + off) =
                pack2h(__float2half_rn(a0), __float2half_rn(a1));
        }
    }

    for (int i = 0; i < NCH; i++) {
        const int s = i & 1;
        CP_WAIT0();
        __syncthreads();

        if (i + 2 < NCH) {
            issue_A(sb, tid, i + 2, xin, b0, hw0, split);
            issue_B(sb, tid, i + 2);
            CP_COMMIT();
        }

        const uint32_t sA = sb + S_A16(s);
        const uint32_t sB = sb + S_B(i % 3);

        {   // ks = 0
            uint32_t Ah[2][4], Bf[8][2];
            #pragma unroll
            for (int mt = 0; mt < 2; mt++) {
                const int row = wm * 32 + mt * 16 + a_r;
                const uint32_t c = (uint32_t)(a_c ^ ((row >> 3) & 3));
                LDM_X4(Ah[mt][0], Ah[mt][1], Ah[mt][2], Ah[mt][3], sA + row * 80 + (c << 4));
            }
            #pragma unroll
            for (int np = 0; np < 4; np++) {
                const int n = wn * 64 + np * 16 + b_n;
                const uint32_t c = (uint32_t)(b_h ^ ((n >> 3) & 3));
                LDM_X4(Bf[2 * np][0], Bf[2 * np][1], Bf[2 * np + 1][0], Bf[2 * np + 1][1],
                       sB + n * 80 + (c << 4));
            }
            #pragma unroll
            for (int mt = 0; mt < 2; mt++)
                #pragma unroll
                for (int nt = 0; nt < 8; nt++)
                    MMA16816(acc[mt][nt], Ah[mt], Bf[nt]);
        }

        if (i + 1 < NCH) {   // convert A16(i+1) in the MMA shadow (safe: waited+synced)
            const unsigned char* raw = smem + S_ARAW((i + 1) % 3);
            #pragma unroll
            for (int j = 0; j < 4; j++) {
                const int kk = 2 * (kq + 4 * j);
                const float a0 = *(const float*)(raw + kk * 256 + mC * 4);
                const float a1 = *(const float*)(raw + (kk + 1) * 256 + mC * 4);
                const uint32_t off = (uint32_t)(mC * 80 + ((j ^ cKey) << 4) + kq * 4);
                *(uint32_t*)(smem + S_A16(s ^ 1) + off) =
                    pack2h(__float2half_rn(a0), __float2half_rn(a1));
            }
        }

        {   // ks = 1
            uint32_t Ah[2][4], Bf[8][2];
            #pragma unroll
            for (int mt = 0; mt < 2; mt++) {
                const int row = wm * 32 + mt * 16 + a_r;
                const uint32_t c = (uint32_t)((2 + a_c) ^ ((row >> 3) & 3));
                LDM_X4(Ah[mt][0], Ah[mt][1], Ah[mt][2], Ah[mt][3], sA + row * 80 + (c << 4));
            }
            #pragma unroll
            for (int np = 0; np < 4; np++) {
                const int n = wn * 64 + np * 16 + b_n;
                const uint32_t c = (uint32_t)((2 + b_h) ^ ((n >> 3) & 3));
                LDM_X4(Bf[2 * np][0], Bf[2 * np][1], Bf[2 * np + 1][0], Bf[2 * np + 1][1],
                       sB + n * 80 + (c << 4));
            }
            #pragma unroll
            for (int mt = 0; mt < 2; mt++)
                #pragma unroll
                for (int nt = 0; nt < 8; nt++)
                    MMA16816(acc[mt][nt], Ah[mt], Bf[nt]);
        }
    }

    __syncthreads();
    const float* bs = (const float*)(smem + S_BIAS);
    const int g  = lid >> 2;
    const int t4 = lid & 3;

    #pragma unroll
    for (int mt = 0; mt < 2; mt++) {
        #pragma unroll
        for (int e = 0; e < 2; e++) {
            const int row = wm * 32 + mt * 16 + g + e * 8;
            const int gmr = m0 + row;
            const int bi  = gmr / HW;
            const int hw  = gmr - bi * HW;
            const int hh  = hw / 38;
            const int wwp = hw - hh * 38;
            float* srow = (float*)(smem + S_STAGE) + row * NOUT;
            #pragma unroll
            for (int nt = 0; nt < 8; nt++) {
                #pragma unroll
                for (int q = 0; q < 2; q++) {
                    const int o = wn * 64 + nt * 8 + t4 * 2 + q;
                    if (o >= NOUT) continue;
                    float v = acc[mt][nt][e * 2 + q] + bs[o];
                    const int ai = (o >= 170) ? 2 : ((o >= 85) ? 1 : 0);
                    const int c  = o - ai * 85;
                    if (c == 0)      v = (1.0f / (1.0f + __expf(-v)) + (float)wwp) * 16.0f;
                    else if (c == 1) v = (1.0f / (1.0f + __expf(-v)) + (float)hh) * 16.0f;
                    else if (c == 2) v = __expf(v) * c_anch[ai][0];
                    else if (c == 3) v = __expf(v) * c_anch[ai][1];
                    srow[o] = v;
                }
            }
        }
    }
    __syncthreads();

    if (tid == 0) {
        asm volatile("fence.proxy.async;" ::: "memory");
        float* gdst = out + (size_t)m0 * NOUT;
        asm volatile("cp.async.bulk.global.shared::cta.bulk_group [%0], [%1], %2;"
                     :: "l"(gdst), "r"(sb + S_STAGE), "r"((uint32_t)(BM * NOUT * 4)) : "memory");
        asm volatile("cp.async.bulk.commit_group;" ::: "memory");
        asm volatile("cp.async.bulk.wait_group 0;" ::: "memory");
    }
}

extern "C" void kernel_launch(void* const* d_in, const int* in_sizes, int n_in,
                              void* d_out, int out_size)
{
    const float* xin    = (const float*)d_in[0];
    const float* conv_w = (const float*)d_in[1];
    const float* conv_b = (const float*)d_in[2];
    float* out = (float*)d_out;

    cudaFuncSetAttribute(yolo_mma_kernel,
                         cudaFuncAttributeMaxDynamicSharedMemorySize, S_TOTAL);
    prep_w<<<512, 256>>>(conv_w);
    yolo_mma_kernel<<<NTILES, THREADS, S_TOTAL>>>(xin, conv_b, out);
}